// round 1
// baseline (speedup 1.0000x reference)
#include <cuda_runtime.h>
#include <cstddef>

#define Bsz  32
#define Tt   1024
#define Ii   1024
#define Hh   256
#define NOUT 512   // 2*H

#define KREG 160   // Whh columns held in registers per thread
#define KSM  96    // Whh columns held in shared memory
#define SCAN_SMEM ((KSM * Hh + 2 * Hh) * 4)   // 100352 bytes

// Scratch (allocation-free rule: __device__ globals)
__device__ float g_xp[(size_t)Tt * Bsz * NOUT];  // input projection (T,B,2H)
__device__ float g_h0[(size_t)Tt * Bsz * NOUT];  // layer-0 output   (T,B,2H)

// ---------------------------------------------------------------------------
// Accurate-enough tanh that is robust to fast-math: MUFU.EX2 based.
// ---------------------------------------------------------------------------
__device__ __forceinline__ float tanh_acc(float z) {
    float az = fabsf(z);
    float e  = exp2f(az * 2.885390081777927f);      // exp(2|z|)
    float r  = 1.0f - __fdividef(2.0f, e + 1.0f);   // tanh(|z|); e=inf -> 1
    return copysignf(r, z);
}

// ---------------------------------------------------------------------------
// Input-projection GEMM:  C(M=32768, N=512) = A(M,K) * W(N,K)^T + b1 + b2
//   mode 0: A rows come from x (B,T,K): row m -> x[m%B][m/B]   (layer 0)
//   mode 1: A rows come from g_h0 (row-major M x K)            (layer 1)
// Output always written to g_xp, row-major (t*B+b, 2H).
// Tiles: BM=64, BN=64, BK=16, 256 threads, 4x4 micro-tile. FMA-pipe bound.
// ---------------------------------------------------------------------------
__global__ __launch_bounds__(256) void gemm_proj(
    const float* __restrict__ A,
    const float* __restrict__ W,
    const float* __restrict__ b1,
    const float* __restrict__ b2,
    int K, int mode)
{
    __shared__ __align__(16) float As[16][68];  // [k][m], padded rows
    __shared__ __align__(16) float Ws[16][68];  // [k][n]

    const int tid = threadIdx.x;
    const int tx  = tid & 15;       // n micro index
    const int ty  = tid >> 4;       // m micro index
    const int m0  = blockIdx.x * 64;
    const int n0  = blockIdx.y * 64;

    // tile loaders: one float4 per thread per operand
    const int ldr = tid >> 2;            // row within tile (0..63)
    const int ldc = (tid & 3) << 2;      // k offset (0,4,8,12)

    const float* Arow;
    {
        int m = m0 + ldr;
        if (mode == 0) {
            int bb = m & (Bsz - 1);
            int t  = m >> 5;             // Bsz == 32
            Arow = A + ((size_t)bb * Tt + t) * K;
        } else {
            Arow = g_h0 + (size_t)m * K;
        }
    }
    const float* Wrow = W + (size_t)(n0 + ldr) * K;

    float acc[4][4];
    #pragma unroll
    for (int i = 0; i < 4; i++)
        #pragma unroll
        for (int j = 0; j < 4; j++) acc[i][j] = 0.0f;

    for (int k0 = 0; k0 < K; k0 += 16) {
        float4 av = *(const float4*)(Arow + k0 + ldc);
        float4 wv = *(const float4*)(Wrow + k0 + ldc);
        As[ldc + 0][ldr] = av.x;  As[ldc + 1][ldr] = av.y;
        As[ldc + 2][ldr] = av.z;  As[ldc + 3][ldr] = av.w;
        Ws[ldc + 0][ldr] = wv.x;  Ws[ldc + 1][ldr] = wv.y;
        Ws[ldc + 2][ldr] = wv.z;  Ws[ldc + 3][ldr] = wv.w;
        __syncthreads();

        #pragma unroll
        for (int kk = 0; kk < 16; kk++) {
            float4 a = *(const float4*)&As[kk][ty * 4];
            float4 w = *(const float4*)&Ws[kk][tx * 4];
            acc[0][0] += a.x * w.x; acc[0][1] += a.x * w.y; acc[0][2] += a.x * w.z; acc[0][3] += a.x * w.w;
            acc[1][0] += a.y * w.x; acc[1][1] += a.y * w.y; acc[1][2] += a.y * w.z; acc[1][3] += a.y * w.w;
            acc[2][0] += a.z * w.x; acc[2][1] += a.z * w.y; acc[2][2] += a.z * w.z; acc[2][3] += a.z * w.w;
            acc[3][0] += a.w * w.x; acc[3][1] += a.w * w.y; acc[3][2] += a.w * w.z; acc[3][3] += a.w * w.w;
        }
        __syncthreads();
    }

    #pragma unroll
    for (int i = 0; i < 4; i++) {
        size_t row = (size_t)(m0 + ty * 4 + i) * NOUT;
        #pragma unroll
        for (int j = 0; j < 4; j++) {
            int n = n0 + tx * 4 + j;
            g_xp[row + n] = acc[i][j] + b1[n] + b2[n];
        }
    }
}

// ---------------------------------------------------------------------------
// Recurrent scan. One CTA per (direction, batch): grid = 64, block = 256.
// Thread j owns output unit j. Whh row j split: k<KREG in registers,
// k>=KREG in smem (stored transposed Wsm[k'][j] -> conflict-free LDS).
// h_prev double-buffered in smem, read as broadcast float4.
//   store_mode 0: write g_h0[(t*B+b)*2H + d*H + j]   (layer 0)
//   store_mode 1: write out [(b*T+t)*2H + d*H + j]   (layer 1 -> d_out)
// ---------------------------------------------------------------------------
__global__ __launch_bounds__(256, 1) void rnn_scan(
    const float* __restrict__ Whh,   // (2,H,H)
    float* __restrict__ outp,        // used when store_mode==1
    int store_mode)
{
    extern __shared__ float smem[];
    float* Wsm  = smem;              // KSM * Hh, layout [k'][j]
    float* hbuf = smem + KSM * Hh;   // 2 * Hh double buffer

    const int tid = threadIdx.x;
    const int d   = blockIdx.x >> 5;
    const int b   = blockIdx.x & 31;
    const float* W = Whh + (size_t)d * Hh * Hh;

    // --- register-resident weight slice: W[tid][0..KREG) ---
    float wreg[KREG];
    {
        const float* wr = W + (size_t)tid * Hh;
        #pragma unroll
        for (int kk = 0; kk < KREG; kk += 4) {
            float4 v = *(const float4*)(wr + kk);
            wreg[kk+0] = v.x; wreg[kk+1] = v.y; wreg[kk+2] = v.z; wreg[kk+3] = v.w;
        }
    }
    // --- smem weight slice, transposed: Wsm[k'*H + j] = W[j][KREG+k'] ---
    for (int idx = tid; idx < KSM * Hh; idx += 256) {
        int j  = idx / KSM;
        int kk = idx - j * KSM;
        Wsm[kk * Hh + j] = W[(size_t)j * Hh + KREG + kk];
    }
    hbuf[tid]      = 0.0f;
    hbuf[Hh + tid] = 0.0f;
    __syncthreads();

    const float* xpb = g_xp + (size_t)b * NOUT + d * Hh + tid;

    int cur = 0;
    #pragma unroll 1
    for (int s = 0; s < Tt; s++) {
        const int t = (d == 0) ? s : (Tt - 1 - s);
        const float xv = __ldg(xpb + (size_t)t * (Bsz * NOUT));

        const float* hc = hbuf + cur * Hh;
        float a0 = 0.0f, a1 = 0.0f, a2 = 0.0f, a3 = 0.0f;

        #pragma unroll
        for (int kk = 0; kk < KREG; kk += 4) {
            float4 h4 = *(const float4*)(hc + kk);
            a0 += wreg[kk+0] * h4.x;
            a1 += wreg[kk+1] * h4.y;
            a2 += wreg[kk+2] * h4.z;
            a3 += wreg[kk+3] * h4.w;
        }
        #pragma unroll
        for (int kk = 0; kk < KSM; kk += 4) {
            float4 h4 = *(const float4*)(hc + KREG + kk);
            a0 += Wsm[(kk+0) * Hh + tid] * h4.x;
            a1 += Wsm[(kk+1) * Hh + tid] * h4.y;
            a2 += Wsm[(kk+2) * Hh + tid] * h4.z;
            a3 += Wsm[(kk+3) * Hh + tid] * h4.w;
        }

        const float z = (a0 + a1) + (a2 + a3) + xv;
        const float h = tanh_acc(z);

        hbuf[(cur ^ 1) * Hh + tid] = h;

        if (store_mode == 0) {
            g_h0[((size_t)t * Bsz + b) * NOUT + d * Hh + tid] = h;
        } else {
            outp[((size_t)b * Tt + t) * NOUT + d * Hh + tid] = h;
        }

        __syncthreads();
        cur ^= 1;
    }
}

// ---------------------------------------------------------------------------
// Launch: gemm0 -> scan0 -> gemm1 -> scan1 (stream-ordered, graph-capturable)
// ---------------------------------------------------------------------------
extern "C" void kernel_launch(void* const* d_in, const int* in_sizes, int n_in,
                              void* d_out, int out_size)
{
    (void)in_sizes; (void)n_in; (void)out_size;
    const float* x    = (const float*)d_in[0];
    const float* Wih0 = (const float*)d_in[1];
    const float* Whh0 = (const float*)d_in[2];
    const float* bih0 = (const float*)d_in[3];
    const float* bhh0 = (const float*)d_in[4];
    const float* Wih1 = (const float*)d_in[5];
    const float* Whh1 = (const float*)d_in[6];
    const float* bih1 = (const float*)d_in[7];
    const float* bhh1 = (const float*)d_in[8];
    float* out = (float*)d_out;

    cudaFuncSetAttribute(rnn_scan, cudaFuncAttributeMaxDynamicSharedMemorySize,
                         SCAN_SMEM);

    dim3 gg(512, 8);  // M/64, 512/64

    // Layer 0
    gemm_proj<<<gg, 256>>>(x, Wih0, bih0, bhh0, Ii, 0);
    rnn_scan<<<64, 256, SCAN_SMEM>>>(Whh0, nullptr, 0);

    // Layer 1 (input = g_h0, K = 512)
    gemm_proj<<<gg, 256>>>(nullptr, Wih1, bih1, bhh1, NOUT, 1);
    rnn_scan<<<64, 256, SCAN_SMEM>>>(Whh1, out, 1);
}

// round 2
// speedup vs baseline: 1.0184x; 1.0184x over previous
#include <cuda_runtime.h>
#include <cstddef>

#define Bsz  32
#define Tt   1024
#define Ii   1024
#define Hh   256
#define NOUT 512   // 2*H

#define KREG 160   // Whh columns held in registers per thread (packed pairs)
#define KSM  96    // Whh columns held in shared memory (packed pairs)
#define SCAN_SMEM ((2 * Hh + KSM * Hh) * 4)   // hbuf + packed Wsm = 100352 B

typedef unsigned long long ull;

// Scratch (allocation-free rule: __device__ globals)
__device__ float g_xp[(size_t)Tt * Bsz * NOUT];  // input projection (T,B,2H)
__device__ float g_h0[(size_t)Tt * Bsz * NOUT];  // layer-0 output   (T,B,2H)

// ---------------------------------------------------------------------------
// Packed f32x2 FMA: d = a*b + d (two independent fp32 lanes per instruction)
// ---------------------------------------------------------------------------
__device__ __forceinline__ void ffma2(ull& acc, ull a, ull b) {
    asm("fma.rn.f32x2 %0, %1, %2, %0;" : "+l"(acc) : "l"(a), "l"(b));
}
__device__ __forceinline__ float2 up2(ull v) {
    float2 r;
    asm("mov.b64 {%0, %1}, %2;" : "=f"(r.x), "=f"(r.y) : "l"(v));
    return r;
}

// ---------------------------------------------------------------------------
// Accurate tanh robust to fast-math: MUFU.EX2 based.
// ---------------------------------------------------------------------------
__device__ __forceinline__ float tanh_acc(float z) {
    float az = fabsf(z);
    float e  = exp2f(az * 2.885390081777927f);      // exp(2|z|)
    float r  = 1.0f - __fdividef(2.0f, e + 1.0f);   // tanh(|z|); e=inf -> 1
    return copysignf(r, z);
}

// ---------------------------------------------------------------------------
// Input-projection GEMM:  C(M=32768, N=512) = A(M,K) * W(N,K)^T + b1 + b2
//   mode 0: A rows from x (B,T,K): row m -> x[m&31][m>>5]   (layer 0)
//   mode 1: A rows from g_h0 (row-major M x K)              (layer 1)
// BM=128, BN=64, BK=16, 256 threads, 8x4 micro-tile of PACKED-k accumulators.
// Smem layout k-contiguous, row stride 18 floats (conflict-free LDS.64).
// ---------------------------------------------------------------------------
#define GS 18   // smem row stride in floats

__global__ __launch_bounds__(256) void gemm_proj(
    const float* __restrict__ A,
    const float* __restrict__ W,
    const float* __restrict__ b1,
    const float* __restrict__ b2,
    int K, int mode)
{
    __shared__ __align__(16) float As[128 * GS];
    __shared__ __align__(16) float Ws[64 * GS];

    const int tid = threadIdx.x;
    const int tx  = tid & 15;       // n lane
    const int ty  = tid >> 4;       // m lane
    const int m0  = blockIdx.x * 128;
    const int n0  = blockIdx.y * 64;

    // ---- loader indexing ----
    // As: 128 rows x 16 k = 512 float4; thread handles idx = tid, tid+256
    const int ar0 = tid >> 2;               // row for idx = tid        (0..63)
    const int ar1 = (tid + 256) >> 2;       // row for idx = tid + 256  (64..127)
    const int akc = (tid & 3) << 2;         // k offset (0,4,8,12)
    // Ws: 64 rows x 16 k = 256 float4; one per thread
    const int wr  = tid >> 2;
    const int wkc = (tid & 3) << 2;

    const float* ArowP0;
    const float* ArowP1;
    if (mode == 0) {
        int m = m0 + ar0;
        ArowP0 = A + ((size_t)(m & 31) * Tt + (m >> 5)) * K;
        m = m0 + ar1;
        ArowP1 = A + ((size_t)(m & 31) * Tt + (m >> 5)) * K;
    } else {
        ArowP0 = g_h0 + (size_t)(m0 + ar0) * K;
        ArowP1 = g_h0 + (size_t)(m0 + ar1) * K;
    }
    const float* WrowP = W + (size_t)(n0 + wr) * K;

    ull acc[8][4];
    #pragma unroll
    for (int i = 0; i < 8; i++)
        #pragma unroll
        for (int j = 0; j < 4; j++) acc[i][j] = 0ull;

    for (int k0 = 0; k0 < K; k0 += 16) {
        float4 a0 = *(const float4*)(ArowP0 + k0 + akc);
        float4 a1 = *(const float4*)(ArowP1 + k0 + akc);
        float4 wv = *(const float4*)(WrowP  + k0 + wkc);
        *(float2*)&As[ar0 * GS + akc]     = make_float2(a0.x, a0.y);
        *(float2*)&As[ar0 * GS + akc + 2] = make_float2(a0.z, a0.w);
        *(float2*)&As[ar1 * GS + akc]     = make_float2(a1.x, a1.y);
        *(float2*)&As[ar1 * GS + akc + 2] = make_float2(a1.z, a1.w);
        *(float2*)&Ws[wr  * GS + wkc]     = make_float2(wv.x, wv.y);
        *(float2*)&Ws[wr  * GS + wkc + 2] = make_float2(wv.z, wv.w);
        __syncthreads();

        #pragma unroll
        for (int kk = 0; kk < 8; kk++) {
            ull a[8], w[4];
            #pragma unroll
            for (int i = 0; i < 8; i++)
                a[i] = *(const ull*)&As[(16 * i + ty) * GS + 2 * kk];
            #pragma unroll
            for (int j = 0; j < 4; j++)
                w[j] = *(const ull*)&Ws[(16 * j + tx) * GS + 2 * kk];
            #pragma unroll
            for (int i = 0; i < 8; i++)
                #pragma unroll
                for (int j = 0; j < 4; j++)
                    ffma2(acc[i][j], a[i], w[j]);
        }
        __syncthreads();
    }

    #pragma unroll
    for (int j = 0; j < 4; j++) {
        const int n = n0 + 16 * j + tx;
        const float bias = b1[n] + b2[n];
        #pragma unroll
        for (int i = 0; i < 8; i++) {
            float2 p = up2(acc[i][j]);
            g_xp[(size_t)(m0 + 16 * i + ty) * NOUT + n] = p.x + p.y + bias;
        }
    }
}

// ---------------------------------------------------------------------------
// Recurrent scan. One CTA per (direction, batch): grid = 64, block = 256.
// Thread j owns output unit j. Whh row j split: k<KREG in registers (packed
// pairs), k>=KREG in smem as packed pairs Wsm2[kp*H + j] (conflict-free
// LDS.64: 16-lane phase covers 128 contiguous bytes).
// ---------------------------------------------------------------------------
__global__ __launch_bounds__(256, 1) void rnn_scan(
    const float* __restrict__ Whh,   // (2,H,H)
    float* __restrict__ outp,        // used when store_mode==1
    int store_mode)
{
    extern __shared__ __align__(16) float smem[];
    float* hbuf = smem;                         // 2 * Hh double buffer
    ull*   Wsm2 = (ull*)(smem + 2 * Hh);        // (KSM/2) * Hh packed pairs

    const int tid = threadIdx.x;
    const int d   = blockIdx.x >> 5;
    const int b   = blockIdx.x & 31;
    const float* W = Whh + (size_t)d * Hh * Hh;

    // --- register-resident weight slice: W[tid][0..KREG) as 80 packed pairs
    ull wreg[KREG / 2];
    {
        const ulonglong2* wrp = (const ulonglong2*)(W + (size_t)tid * Hh);
        #pragma unroll
        for (int q = 0; q < KREG / 4; q++) {
            ulonglong2 v = wrp[q];
            wreg[2 * q]     = v.x;
            wreg[2 * q + 1] = v.y;
        }
    }
    // --- smem weight slice: Wsm2[kp*H + j] = pack(W[j][KREG+2kp], W[j][KREG+2kp+1])
    {
        const float2* wsp = (const float2*)(W + (size_t)tid * Hh + KREG);
        #pragma unroll
        for (int kp = 0; kp < KSM / 2; kp++) {
            float2 v = wsp[kp];
            ull pv;
            asm("mov.b64 %0, {%1, %2};" : "=l"(pv) : "f"(v.x), "f"(v.y));
            Wsm2[kp * Hh + tid] = pv;
        }
    }
    hbuf[tid]      = 0.0f;
    hbuf[Hh + tid] = 0.0f;
    __syncthreads();

    const float* xpb = g_xp + (size_t)b * NOUT + d * Hh + tid;

    int cur = 0;
    #pragma unroll 1
    for (int s = 0; s < Tt; s++) {
        const int t = (d == 0) ? s : (Tt - 1 - s);
        const float xv = __ldg(xpb + (size_t)t * (Bsz * NOUT));

        const float* hc = hbuf + cur * Hh;
        ull acc0 = 0ull, acc1 = 0ull;

        // register part: 40 x (ulonglong2 h load + 2 FFMA2)
        const ulonglong2* h2p = (const ulonglong2*)hc;
        #pragma unroll
        for (int q = 0; q < KREG / 4; q++) {
            ulonglong2 h2 = h2p[q];
            ffma2(acc0, wreg[2 * q],     h2.x);
            ffma2(acc1, wreg[2 * q + 1], h2.y);
        }
        // smem part: 48 packed pairs, alternating accumulators
        const ull* hs = (const ull*)(hc + KREG);
        #pragma unroll
        for (int kp = 0; kp < KSM / 2; kp += 2) {
            ffma2(acc0, Wsm2[kp * Hh + tid],       hs[kp]);
            ffma2(acc1, Wsm2[(kp + 1) * Hh + tid], hs[kp + 1]);
        }

        float2 p0 = up2(acc0);
        float2 p1 = up2(acc1);
        const float z = ((p0.x + p0.y) + (p1.x + p1.y)) + xv;
        const float h = tanh_acc(z);

        hbuf[(cur ^ 1) * Hh + tid] = h;

        if (store_mode == 0) {
            g_h0[((size_t)t * Bsz + b) * NOUT + d * Hh + tid] = h;
        } else {
            outp[((size_t)b * Tt + t) * NOUT + d * Hh + tid] = h;
        }

        __syncthreads();
        cur ^= 1;
    }
}

// ---------------------------------------------------------------------------
// Launch: gemm0 -> scan0 -> gemm1 -> scan1 (stream-ordered, graph-capturable)
// ---------------------------------------------------------------------------
extern "C" void kernel_launch(void* const* d_in, const int* in_sizes, int n_in,
                              void* d_out, int out_size)
{
    (void)in_sizes; (void)n_in; (void)out_size;
    const float* x    = (const float*)d_in[0];
    const float* Wih0 = (const float*)d_in[1];
    const float* Whh0 = (const float*)d_in[2];
    const float* bih0 = (const float*)d_in[3];
    const float* bhh0 = (const float*)d_in[4];
    const float* Wih1 = (const float*)d_in[5];
    const float* Whh1 = (const float*)d_in[6];
    const float* bih1 = (const float*)d_in[7];
    const float* bhh1 = (const float*)d_in[8];
    float* out = (float*)d_out;

    cudaFuncSetAttribute(rnn_scan, cudaFuncAttributeMaxDynamicSharedMemorySize,
                         SCAN_SMEM);

    dim3 gg(Bsz * Tt / 128, NOUT / 64);  // (256, 8)

    // Layer 0
    gemm_proj<<<gg, 256>>>(x, Wih0, bih0, bhh0, Ii, 0);
    rnn_scan<<<64, 256, SCAN_SMEM>>>(Whh0, nullptr, 0);

    // Layer 1 (input = g_h0, K = 512)
    gemm_proj<<<gg, 256>>>(nullptr, Wih1, bih1, bhh1, NOUT, 1);
    rnn_scan<<<64, 256, SCAN_SMEM>>>(Whh1, out, 1);
}

// round 4
// speedup vs baseline: 1.3104x; 1.2867x over previous
#include <cuda_runtime.h>
#include <cstddef>
#include <cstdint>

#define Bsz  32
#define Tt   1024
#define Ii   1024
#define Hh   256
#define NOUT 512   // 2*H

typedef unsigned long long ull;

// Scratch (allocation-free rule: __device__ globals)
__device__ float g_xp[(size_t)Tt * Bsz * NOUT];  // input projection (t*B+b, 2H)
__device__ float g_h0[(size_t)Tt * Bsz * NOUT];  // layer-0 output   (t*B+b, 2H)

// ---------------------------------------------------------------------------
// Packed f32x2 FMA helpers
// ---------------------------------------------------------------------------
__device__ __forceinline__ void ffma2(ull& acc, ull a, ull b) {
    asm("fma.rn.f32x2 %0, %1, %2, %0;" : "+l"(acc) : "l"(a), "l"(b));
}
__device__ __forceinline__ float2 up2(ull v) {
    float2 r;
    asm("mov.b64 {%0, %1}, %2;" : "=f"(r.x), "=f"(r.y) : "l"(v));
    return r;
}

// Accurate tanh robust to fast-math (MUFU.EX2 based)
__device__ __forceinline__ float tanh_acc(float z) {
    float az = fabsf(z);
    float e  = exp2f(az * 2.885390081777927f);      // exp(2|z|)
    float r  = 1.0f - __fdividef(2.0f, e + 1.0f);
    return copysignf(r, z);
}

__device__ __forceinline__ uint32_t smem_u32(const void* p) {
    uint32_t a;
    asm("{ .reg .u64 t; cvta.to.shared.u64 t, %1; cvt.u32.u64 %0, t; }"
        : "=r"(a) : "l"(p));
    return a;
}
__device__ __forceinline__ uint32_t ctarank() {
    uint32_t r;
    asm("mov.u32 %0, %%cluster_ctarank;" : "=r"(r));
    return r;
}
__device__ __forceinline__ uint32_t mapa_u32(uint32_t laddr, uint32_t trank) {
    uint32_t r;
    asm("mapa.shared::cluster.u32 %0, %1, %2;" : "=r"(r) : "r"(laddr), "r"(trank));
    return r;
}
__device__ __forceinline__ void st_remote_f32(uint32_t raddr, float v) {
    asm volatile("st.shared::cluster.f32 [%0], %1;" :: "r"(raddr), "f"(v) : "memory");
}
__device__ __forceinline__ void mbar_arrive_rel_cluster(uint32_t raddr) {
    asm volatile("mbarrier.arrive.release.cluster.shared::cluster.b64 _, [%0];"
                 :: "r"(raddr) : "memory");
}
__device__ __forceinline__ void mbar_wait_acq_cluster(uint32_t mbar, uint32_t parity) {
    asm volatile(
        "{\n\t"
        ".reg .pred P;\n\t"
        "W%=:\n\t"
        "mbarrier.try_wait.parity.acquire.cluster.shared::cta.b64 P, [%0], %1, 0x989680;\n\t"
        "@P bra.uni D%=;\n\t"
        "bra.uni W%=;\n\t"
        "D%=:\n\t"
        "}" :: "r"(mbar), "r"(parity) : "memory");
}

// ---------------------------------------------------------------------------
// Input-projection GEMM: C(32768, 512) = A * W^T + b1 + b2
// BM=BN=128, BK=16, 256 threads, 8x8 packed-k micro-tile, double-buffered.
//   mode 0: A row m -> x[m&31][m>>5]  (layer 0, K=1024)
//   mode 1: A row m -> g_h0[m]        (layer 1, K=512)
// ---------------------------------------------------------------------------
#define GS 18   // smem row stride in floats (conflict-free LDS.64)

__global__ __launch_bounds__(256) void gemm_proj(
    const float* __restrict__ A,
    const float* __restrict__ W,
    const float* __restrict__ b1,
    const float* __restrict__ b2,
    int K, int mode)
{
    __shared__ __align__(16) float As[2][128 * GS];
    __shared__ __align__(16) float Ws[2][128 * GS];

    const int tid = threadIdx.x;
    const int tx  = tid & 15;       // n lane
    const int ty  = tid >> 4;       // m lane
    const int m0  = blockIdx.x * 128;
    const int n0  = blockIdx.y * 128;

    // loader: 512 float4 per operand tile, 2 per thread (rows lr, lr+64)
    const int lr = tid >> 2;
    const int lk = (tid & 3) << 2;

    const float* Ar0;
    const float* Ar1;
    if (mode == 0) {
        int m = m0 + lr;
        Ar0 = A + ((size_t)(m & 31) * Tt + (m >> 5)) * K;
        m = m0 + lr + 64;
        Ar1 = A + ((size_t)(m & 31) * Tt + (m >> 5)) * K;
    } else {
        Ar0 = g_h0 + (size_t)(m0 + lr) * K;
        Ar1 = g_h0 + (size_t)(m0 + lr + 64) * K;
    }
    const float* Wr0 = W + (size_t)(n0 + lr) * K;
    const float* Wr1 = W + (size_t)(n0 + lr + 64) * K;

    ull acc[8][8];
    #pragma unroll
    for (int i = 0; i < 8; i++)
        #pragma unroll
        for (int j = 0; j < 8; j++) acc[i][j] = 0ull;

    const int nkt = K >> 4;

    // prologue: tile 0 -> buffer 0
    float4 pa0 = *(const float4*)(Ar0 + lk);
    float4 pa1 = *(const float4*)(Ar1 + lk);
    float4 pw0 = *(const float4*)(Wr0 + lk);
    float4 pw1 = *(const float4*)(Wr1 + lk);
    *(float2*)&As[0][lr * GS + lk]            = make_float2(pa0.x, pa0.y);
    *(float2*)&As[0][lr * GS + lk + 2]        = make_float2(pa0.z, pa0.w);
    *(float2*)&As[0][(lr + 64) * GS + lk]     = make_float2(pa1.x, pa1.y);
    *(float2*)&As[0][(lr + 64) * GS + lk + 2] = make_float2(pa1.z, pa1.w);
    *(float2*)&Ws[0][lr * GS + lk]            = make_float2(pw0.x, pw0.y);
    *(float2*)&Ws[0][lr * GS + lk + 2]        = make_float2(pw0.z, pw0.w);
    *(float2*)&Ws[0][(lr + 64) * GS + lk]     = make_float2(pw1.x, pw1.y);
    *(float2*)&Ws[0][(lr + 64) * GS + lk + 2] = make_float2(pw1.z, pw1.w);
    __syncthreads();

    for (int kt = 0; kt < nkt; kt++) {
        const int cb = kt & 1;
        const bool more = (kt + 1 < nkt);
        if (more) {
            const int ko = (kt + 1) << 4;
            pa0 = *(const float4*)(Ar0 + ko + lk);
            pa1 = *(const float4*)(Ar1 + ko + lk);
            pw0 = *(const float4*)(Wr0 + ko + lk);
            pw1 = *(const float4*)(Wr1 + ko + lk);
        }

        #pragma unroll
        for (int kk = 0; kk < 8; kk++) {
            ull a[8], w[8];
            #pragma unroll
            for (int i = 0; i < 8; i++)
                a[i] = *(const ull*)&As[cb][(16 * i + ty) * GS + 2 * kk];
            #pragma unroll
            for (int j = 0; j < 8; j++)
                w[j] = *(const ull*)&Ws[cb][(16 * j + tx) * GS + 2 * kk];
            #pragma unroll
            for (int i = 0; i < 8; i++)
                #pragma unroll
                for (int j = 0; j < 8; j++)
                    ffma2(acc[i][j], a[i], w[j]);
        }

        if (more) {
            const int nb = cb ^ 1;
            *(float2*)&As[nb][lr * GS + lk]            = make_float2(pa0.x, pa0.y);
            *(float2*)&As[nb][lr * GS + lk + 2]        = make_float2(pa0.z, pa0.w);
            *(float2*)&As[nb][(lr + 64) * GS + lk]     = make_float2(pa1.x, pa1.y);
            *(float2*)&As[nb][(lr + 64) * GS + lk + 2] = make_float2(pa1.z, pa1.w);
            *(float2*)&Ws[nb][lr * GS + lk]            = make_float2(pw0.x, pw0.y);
            *(float2*)&Ws[nb][lr * GS + lk + 2]        = make_float2(pw0.z, pw0.w);
            *(float2*)&Ws[nb][(lr + 64) * GS + lk]     = make_float2(pw1.x, pw1.y);
            *(float2*)&Ws[nb][(lr + 64) * GS + lk + 2] = make_float2(pw1.z, pw1.w);
        }
        __syncthreads();
    }

    #pragma unroll
    for (int j = 0; j < 8; j++) {
        const int n = n0 + 16 * j + tx;
        const float bias = b1[n] + b2[n];
        #pragma unroll
        for (int i = 0; i < 8; i++) {
            float2 p = up2(acc[i][j]);
            g_xp[(size_t)(m0 + 16 * i + ty) * NOUT + n] = p.x + p.y + bias;
        }
    }
}

// ---------------------------------------------------------------------------
// Recurrent scan, cluster-of-2. Grid = 128 CTAs (64 clusters), 256 threads.
// Cluster pair p = blockIdx>>1 -> (d = p>>5, b = p&31). CTA rank r computes
// outputs j in [r*128, r*128+128). Thread t: output jl = t&127, k-half
// c = t>>7 (128 k-values, all weights in 64 packed regs).
// Partial sums combined in smem; h halves exchanged via DSMEM + mbarrier.
// ---------------------------------------------------------------------------
__global__ __launch_bounds__(256, 1) __cluster_dims__(2, 1, 1)
void rnn_scan(const float* __restrict__ Whh,
              float* __restrict__ outp,
              int store_mode)
{
    __shared__ __align__(16) float hbuf[2][Hh];
    __shared__ __align__(16) float part[256];
    __shared__ __align__(8)  ull   mbar;

    const int tid  = threadIdx.x;
    const uint32_t rank = ctarank();
    const int pair = blockIdx.x >> 1;
    const int d    = pair >> 5;
    const int b    = pair & 31;
    const int jl   = tid & 127;
    const int c    = tid >> 7;
    const int j    = (int)rank * 128 + jl;

    // weights: W[d][j][c*128 .. c*128+128) -> 64 packed ull in registers
    ull wreg[64];
    {
        const ulonglong2* wr =
            (const ulonglong2*)(Whh + ((size_t)d * Hh + j) * Hh + c * 128);
        #pragma unroll
        for (int q = 0; q < 32; q++) {
            ulonglong2 v = wr[q];
            wreg[2 * q]     = v.x;
            wreg[2 * q + 1] = v.y;
        }
    }

    hbuf[0][tid] = 0.0f;
    hbuf[1][tid] = 0.0f;

    const uint32_t mb = smem_u32(&mbar);
    if (tid == 0) {
        asm volatile("mbarrier.init.shared.b64 [%0], %1;" :: "r"(mb), "r"(128) : "memory");
    }
    __syncthreads();
    asm volatile("barrier.cluster.arrive.aligned;" ::: "memory");
    asm volatile("barrier.cluster.wait.aligned;" ::: "memory");

    // remote addresses (peer CTA): my h slots in peer's hbuf, peer's mbar
    const uint32_t peer = rank ^ 1u;
    uint32_t remH0 = 0, remH1 = 0;
    const uint32_t remMb = mapa_u32(mb, peer);
    if (tid < 128) {
        remH0 = mapa_u32(smem_u32(&hbuf[0][rank * 128 + tid]), peer);
        remH1 = mapa_u32(smem_u32(&hbuf[1][rank * 128 + tid]), peer);
    }

    // xp pointer for this thread's output column (valid for tid<128)
    const int xcol  = d * Hh + (int)rank * 128 + tid;   // tid==jl when tid<128
    const int dstep = (d ? -1 : 1) * (Bsz * NOUT);
    const float* xp = g_xp + (size_t)(d ? (Tt - 1) : 0) * (Bsz * NOUT)
                           + (size_t)b * NOUT + xcol;
    float xv = (tid < 128) ? __ldg(xp) : 0.0f;

    int cur = 0;
    uint32_t ph = 0;

    #pragma unroll 1
    for (int s = 0; s < Tt; s++) {
        // ---- partial matvec: 128 k-values (32 ulonglong2 h-loads, 64 FFMA2)
        ull a0 = 0ull, a1 = 0ull, a2 = 0ull, a3 = 0ull;
        const ulonglong2* hp = (const ulonglong2*)&hbuf[cur][c * 128];
        #pragma unroll
        for (int q = 0; q < 32; q += 2) {
            ulonglong2 h0 = hp[q];
            ulonglong2 h1 = hp[q + 1];
            ffma2(a0, wreg[2 * q],     h0.x);
            ffma2(a1, wreg[2 * q + 1], h0.y);
            ffma2(a2, wreg[2 * q + 2], h1.x);
            ffma2(a3, wreg[2 * q + 3], h1.y);
        }
        float2 p0 = up2(a0), p1 = up2(a1), p2 = up2(a2), p3 = up2(a3);
        part[tid] = ((p0.x + p0.y) + (p1.x + p1.y))
                  + ((p2.x + p2.y) + (p3.x + p3.y));
        __syncthreads();

        if (tid < 128) {
            const float z = part[tid] + part[tid + 128] + xv;
            const float h = tanh_acc(z);
            const int t = d ? (Tt - 1 - s) : s;
            const int nb = cur ^ 1;

            hbuf[nb][rank * 128 + tid] = h;            // local half
            st_remote_f32(nb ? remH1 : remH0, h);      // peer half
            mbar_arrive_rel_cluster(remMb);            // signal peer

            if (store_mode == 0)
                g_h0[((size_t)t * Bsz + b) * NOUT + xcol] = h;
            else
                outp[((size_t)b * Tt + t) * NOUT + xcol] = h;

            if (s + 1 < Tt) {
                xp += dstep;
                xv = __ldg(xp);
            }
        }
        __syncthreads();                // local half + part[] reuse
        mbar_wait_acq_cluster(mb, ph);  // remote half arrived
        ph ^= 1u;
        cur ^= 1;
    }

    asm volatile("barrier.cluster.arrive.aligned;" ::: "memory");
    asm volatile("barrier.cluster.wait.aligned;" ::: "memory");
}

// ---------------------------------------------------------------------------
// Launch: gemm0 -> scan0 -> gemm1 -> scan1
// ---------------------------------------------------------------------------
extern "C" void kernel_launch(void* const* d_in, const int* in_sizes, int n_in,
                              void* d_out, int out_size)
{
    (void)in_sizes; (void)n_in; (void)out_size;
    const float* x    = (const float*)d_in[0];
    const float* Wih0 = (const float*)d_in[1];
    const float* Whh0 = (const float*)d_in[2];
    const float* bih0 = (const float*)d_in[3];
    const float* bhh0 = (const float*)d_in[4];
    const float* Wih1 = (const float*)d_in[5];
    const float* Whh1 = (const float*)d_in[6];
    const float* bih1 = (const float*)d_in[7];
    const float* bhh1 = (const float*)d_in[8];
    float* out = (float*)d_out;

    dim3 gg(Bsz * Tt / 128, NOUT / 128);  // (256, 4)

    gemm_proj<<<gg, 256>>>(x, Wih0, bih0, bhh0, Ii, 0);
    rnn_scan<<<128, 256>>>(Whh0, nullptr, 0);

    gemm_proj<<<gg, 256>>>(nullptr, Wih1, bih1, bhh1, NOUT, 1);
    rnn_scan<<<128, 256>>>(Whh1, out, 1);
}

// round 6
// speedup vs baseline: 1.6317x; 1.2452x over previous
#include <cuda_runtime.h>
#include <cuda_bf16.h>
#include <cstddef>
#include <cstdint>

#define Bsz  32
#define Tt   1024
#define Ii   1024
#define Hh   256
#define NOUT 512   // 2*H
#define Mrows (Bsz * Tt)        // 32768
#define NKT0 16                 // 1024/64 k-tiles (layer0)
#define NKT1 8                  // 512/64 k-tiles (layer1)
#define TILEB 16384             // bytes per 128x64 bf16 tile
#define STAGEB 65536            // 4 tiles (Ahi,Alo,Whi,Wlo)
#define GEMM_SMEM (2 * STAGEB + 1024)

typedef unsigned long long ull;

// ---------------------------------------------------------------------------
// Device scratch (allocation-free rule: __device__ globals)
// ---------------------------------------------------------------------------
__device__ float g_xp[(size_t)Mrows * NOUT];                 // projections
__device__ __align__(256) __nv_bfloat16 g_Ahi[(size_t)Mrows * Ii];
__device__ __align__(256) __nv_bfloat16 g_Alo[(size_t)Mrows * Ii];
__device__ __align__(256) __nv_bfloat16 g_H1hi[(size_t)Mrows * NOUT];
__device__ __align__(256) __nv_bfloat16 g_H1lo[(size_t)Mrows * NOUT];
__device__ __align__(256) __nv_bfloat16 g_W0hi[NOUT * Ii];
__device__ __align__(256) __nv_bfloat16 g_W0lo[NOUT * Ii];
__device__ __align__(256) __nv_bfloat16 g_W1hi[NOUT * NOUT];
__device__ __align__(256) __nv_bfloat16 g_W1lo[NOUT * NOUT];

// ---------------------------------------------------------------------------
// Helpers
// ---------------------------------------------------------------------------
__device__ __forceinline__ uint32_t swz(uint32_t x) { return x ^ ((x >> 3) & 0x70); }

__device__ __forceinline__ void ffma2(ull& acc, ull a, ull b) {
    asm("fma.rn.f32x2 %0, %1, %2, %0;" : "+l"(acc) : "l"(a), "l"(b));
}
__device__ __forceinline__ float2 up2(ull v) {
    float2 r;
    asm("mov.b64 {%0, %1}, %2;" : "=f"(r.x), "=f"(r.y) : "l"(v));
    return r;
}
__device__ __forceinline__ float tanh_acc(float z) {
    float az = fabsf(z);
    float e  = exp2f(az * 2.885390081777927f);
    float r  = 1.0f - __fdividef(2.0f, e + 1.0f);
    return copysignf(r, z);
}
__device__ __forceinline__ uint32_t smem_u32(const void* p) {
    uint32_t a;
    asm("{ .reg .u64 t; cvta.to.shared.u64 t, %1; cvt.u32.u64 %0, t; }"
        : "=r"(a) : "l"(p));
    return a;
}
__device__ __forceinline__ uint32_t ctarank() {
    uint32_t r;
    asm("mov.u32 %0, %%cluster_ctarank;" : "=r"(r));
    return r;
}
__device__ __forceinline__ uint32_t mapa_u32(uint32_t laddr, uint32_t trank) {
    uint32_t r;
    asm("mapa.shared::cluster.u32 %0, %1, %2;" : "=r"(r) : "r"(laddr), "r"(trank));
    return r;
}
__device__ __forceinline__ void st_remote_f32(uint32_t raddr, float v) {
    asm volatile("st.shared::cluster.f32 [%0], %1;" :: "r"(raddr), "f"(v) : "memory");
}
__device__ __forceinline__ void mbar_arrive_rel_cluster(uint32_t raddr) {
    asm volatile("mbarrier.arrive.release.cluster.shared::cluster.b64 _, [%0];"
                 :: "r"(raddr) : "memory");
}
__device__ __forceinline__ void mbar_wait_acq_cluster(uint32_t mbar, uint32_t parity) {
    asm volatile(
        "{\n\t.reg .pred P;\n\t"
        "W%=:\n\t"
        "mbarrier.try_wait.parity.acquire.cluster.shared::cta.b64 P, [%0], %1, 0x989680;\n\t"
        "@P bra.uni D%=;\n\tbra.uni W%=;\n\tD%=:\n\t}"
        :: "r"(mbar), "r"(parity) : "memory");
}
#define MBARRIER_INIT(addr, cnt) \
    asm volatile("mbarrier.init.shared.b64 [%0], %1;" :: "r"(addr), "r"(cnt) : "memory")

// generic tensor-core path (compute_80+ PTX, compiles at compute_103)
__device__ __forceinline__ void ldsm4(uint32_t* r, uint32_t addr) {
    asm volatile("ldmatrix.sync.aligned.m8n8.x4.shared.b16 {%0,%1,%2,%3}, [%4];"
                 : "=r"(r[0]), "=r"(r[1]), "=r"(r[2]), "=r"(r[3]) : "r"(addr));
}
__device__ __forceinline__ void mma_bf16(float* c, const uint32_t* a,
                                         uint32_t b0, uint32_t b1) {
    asm volatile(
        "mma.sync.aligned.m16n8k16.row.col.f32.bf16.bf16.f32 "
        "{%0,%1,%2,%3}, {%4,%5,%6,%7}, {%8,%9}, {%0,%1,%2,%3};"
        : "+f"(c[0]), "+f"(c[1]), "+f"(c[2]), "+f"(c[3])
        : "r"(a[0]), "r"(a[1]), "r"(a[2]), "r"(a[3]), "r"(b0), "r"(b1));
}
__device__ __forceinline__ void cp16(uint32_t sdst, const void* gsrc) {
    asm volatile("cp.async.cg.shared.global [%0], [%1], 16;"
                 :: "r"(sdst), "l"(gsrc) : "memory");
}
#define CP_COMMIT() asm volatile("cp.async.commit_group;" ::: "memory")
#define CP_WAIT(n)  asm volatile("cp.async.wait_group %0;" :: "n"(n) : "memory")

// ---------------------------------------------------------------------------
// fp32 -> (hi, lo) bf16 split, written into SW128-swizzled 128x64 tiles.
// mode 0: row m of A comes from x[m&31][m>>5]; mode 1: row m = src row m.
// ---------------------------------------------------------------------------
__global__ __launch_bounds__(256) void conv_bf16(
    const float* __restrict__ src,
    __nv_bfloat16* __restrict__ dhi,
    __nv_bfloat16* __restrict__ dlo,
    int K, int mode, int total)
{
    int idx = blockIdx.x * 256 + threadIdx.x;
    if (idx >= total) return;
    const int gpr = K >> 3;
    const int m = idx / gpr;
    const int k = (idx - m * gpr) << 3;

    const float* s = (mode == 0)
        ? src + (((size_t)(m & 31) * Tt + (m >> 5)) * K + k)
        : src + ((size_t)m * K + k);
    float4 v0 = *(const float4*)s;
    float4 v1 = *(const float4*)(s + 4);
    float f[8] = {v0.x, v0.y, v0.z, v0.w, v1.x, v1.y, v1.z, v1.w};

    uint32_t hw[4], lw[4];
    #pragma unroll
    for (int i = 0; i < 4; i++) {
        __nv_bfloat16 ha = __float2bfloat16_rn(f[2 * i]);
        __nv_bfloat16 hb = __float2bfloat16_rn(f[2 * i + 1]);
        __nv_bfloat16 la = __float2bfloat16_rn(f[2 * i]     - __bfloat162float(ha));
        __nv_bfloat16 lb = __float2bfloat16_rn(f[2 * i + 1] - __bfloat162float(hb));
        hw[i] = (uint32_t)__bfloat16_as_ushort(ha) | ((uint32_t)__bfloat16_as_ushort(hb) << 16);
        lw[i] = (uint32_t)__bfloat16_as_ushort(la) | ((uint32_t)__bfloat16_as_ushort(lb) << 16);
    }

    const int mt = m >> 7, r = m & 127, kt = k >> 6, c = k & 63;
    size_t off = ((size_t)(mt * (K >> 6) + kt)) * TILEB + swz((uint32_t)(r * 128 + c * 2));
    *(uint4*)((char*)dhi + off) = make_uint4(hw[0], hw[1], hw[2], hw[3]);
    *(uint4*)((char*)dlo + off) = make_uint4(lw[0], lw[1], lw[2], lw[3]);
}

// ---------------------------------------------------------------------------
// bf16x3 tensor-core GEMM (mma.sync): g_xp = A.W^T + b1 + b2
// CTA 128x128, 8 warps (2m x 4n), warp tile 64x32, K staged 64 wide,
// cp.async double-buffered. Tiles pre-swizzled in gmem.
// ---------------------------------------------------------------------------
__device__ __forceinline__ void stage_cp(
    uint32_t sdst, const char* pAh, const char* pAl,
    const char* pWh, const char* pWl, int tid)
{
    #pragma unroll
    for (int i = 0; i < 4; i++) {
        const int off = tid * 16 + i * 4096;
        cp16(sdst + off,         pAh + off);
        cp16(sdst + 16384 + off, pAl + off);
        cp16(sdst + 32768 + off, pWh + off);
        cp16(sdst + 49152 + off, pWl + off);
    }
    CP_COMMIT();
}

__global__ __launch_bounds__(256, 1) void gemm_tc(
    const __nv_bfloat16* __restrict__ Ahi, const __nv_bfloat16* __restrict__ Alo,
    const __nv_bfloat16* __restrict__ Whi, const __nv_bfloat16* __restrict__ Wlo,
    const float* __restrict__ b1, const float* __restrict__ b2, int NKT)
{
    extern __shared__ __align__(16) char dsm[];
    char* bp = dsm + ((1024u - (smem_u32(dsm) & 1023u)) & 1023u);

    const int tid  = threadIdx.x;
    const int lane = tid & 31;
    const int wid  = tid >> 5;
    const int nt = blockIdx.x;
    const int mt = blockIdx.y;

    const int wm = (wid >> 2) * 64;   // warp m offset (0/64)
    const int wn = (wid & 3) * 32;    // warp n offset (0/32/64/96)

    // ldmatrix per-lane address components (byte offsets within a tile)
    const int a_row = lane & 15;
    const int a_cb  = (lane >> 4) * 16;
    const int b_row = (lane & 7) + ((lane >> 4) << 3);
    const int b_cb  = (lane & 8) ? 16 : 0;

    const char* gAh = (const char*)Ahi + (size_t)mt * NKT * TILEB;
    const char* gAl = (const char*)Alo + (size_t)mt * NKT * TILEB;
    const char* gWh = (const char*)Whi + (size_t)nt * NKT * TILEB;
    const char* gWl = (const char*)Wlo + (size_t)nt * NKT * TILEB;

    const uint32_t s0 = smem_u32(bp);

    float acc[4][4][4];
    #pragma unroll
    for (int i = 0; i < 4; i++)
        #pragma unroll
        for (int j = 0; j < 4; j++)
            #pragma unroll
            for (int e = 0; e < 4; e++) acc[i][j][e] = 0.0f;

    // prologue: stages 0, 1
    stage_cp(s0, gAh, gAl, gWh, gWl, tid);
    if (NKT > 1)
        stage_cp(s0 + STAGEB, gAh + TILEB, gAl + TILEB, gWh + TILEB, gWl + TILEB, tid);

    for (int kt = 0; kt < NKT; kt++) {
        if (kt + 1 < NKT) CP_WAIT(1); else CP_WAIT(0);
        __syncthreads();

        const uint32_t sb = s0 + (kt & 1) * STAGEB;

        #pragma unroll
        for (int kc = 0; kc < 4; kc++) {
            const int kb = kc * 32;   // byte offset of k16 chunk
            uint32_t ah[4][4], al[4][4], bh[2][4], bl[2][4];
            #pragma unroll
            for (int mi = 0; mi < 4; mi++) {
                uint32_t off = swz((uint32_t)((wm + mi * 16 + a_row) * 128 + a_cb + kb));
                ldsm4(ah[mi], sb + off);
                ldsm4(al[mi], sb + 16384 + off);
            }
            #pragma unroll
            for (int p = 0; p < 2; p++) {
                uint32_t off = swz((uint32_t)((wn + p * 16 + b_row) * 128 + b_cb + kb));
                ldsm4(bh[p], sb + 32768 + off);
                ldsm4(bl[p], sb + 49152 + off);
            }
            #pragma unroll
            for (int mi = 0; mi < 4; mi++) {
                #pragma unroll
                for (int nj = 0; nj < 4; nj++) {
                    const int p = nj >> 1, h = (nj & 1) * 2;
                    mma_bf16(acc[mi][nj], ah[mi], bh[p][h], bh[p][h + 1]);
                    mma_bf16(acc[mi][nj], ah[mi], bl[p][h], bl[p][h + 1]);
                    mma_bf16(acc[mi][nj], al[mi], bh[p][h], bh[p][h + 1]);
                }
            }
        }

        if (kt + 2 < NKT) {
            __syncthreads();   // all warps done reading this buffer
            const size_t tb = (size_t)(kt + 2) * TILEB;
            stage_cp(s0 + (kt & 1) * STAGEB,
                     gAh + tb, gAl + tb, gWh + tb, gWl + tb, tid);
        }
    }
    __syncthreads();

    // bias into (now free) smem
    float* bias_s = (float*)bp;
    if (tid < 128) bias_s[tid] = b1[nt * 128 + tid] + b2[nt * 128 + tid];
    __syncthreads();

    const int g = lane >> 2, cp2 = (lane & 3) * 2;
    #pragma unroll
    for (int mi = 0; mi < 4; mi++) {
        #pragma unroll
        for (int nj = 0; nj < 4; nj++) {
            const int col = wn + nj * 8 + cp2;
            const float bx = bias_s[col], by = bias_s[col + 1];
            const size_t r0 = (size_t)(mt * 128 + wm + mi * 16 + g) * NOUT + nt * 128 + col;
            const size_t r1 = r0 + 8 * NOUT;
            *(float2*)(g_xp + r0) = make_float2(acc[mi][nj][0] + bx, acc[mi][nj][1] + by);
            *(float2*)(g_xp + r1) = make_float2(acc[mi][nj][2] + bx, acc[mi][nj][3] + by);
        }
    }
}

// ---------------------------------------------------------------------------
// Recurrent scan, cluster-of-2 (unchanged design; store_mode 0 emits hi/lo
// bf16 swizzled tiles for the layer-1 GEMM, store_mode 1 writes d_out fp32).
// ---------------------------------------------------------------------------
__global__ __launch_bounds__(256, 1) __cluster_dims__(2, 1, 1)
void rnn_scan(const float* __restrict__ Whh,
              float* __restrict__ outp,
              int store_mode)
{
    __shared__ __align__(16) float hbuf[2][Hh];
    __shared__ __align__(16) float part[256];
    __shared__ __align__(8)  ull   mbar;

    const int tid  = threadIdx.x;
    const uint32_t rank = ctarank();
    const int pair = blockIdx.x >> 1;
    const int d    = pair >> 5;
    const int b    = pair & 31;
    const int jl   = tid & 127;
    const int c    = tid >> 7;
    const int j    = (int)rank * 128 + jl;

    ull wreg[64];
    {
        const ulonglong2* wr =
            (const ulonglong2*)(Whh + ((size_t)d * Hh + j) * Hh + c * 128);
        #pragma unroll
        for (int q = 0; q < 32; q++) {
            ulonglong2 v = wr[q];
            wreg[2 * q]     = v.x;
            wreg[2 * q + 1] = v.y;
        }
    }

    hbuf[0][tid] = 0.0f;
    hbuf[1][tid] = 0.0f;

    const uint32_t mb = smem_u32(&mbar);
    if (tid == 0) MBARRIER_INIT(mb, 128);
    __syncthreads();
    asm volatile("barrier.cluster.arrive.aligned;" ::: "memory");
    asm volatile("barrier.cluster.wait.aligned;" ::: "memory");

    const uint32_t peer = rank ^ 1u;
    uint32_t remH0 = 0, remH1 = 0;
    const uint32_t remMb = mapa_u32(mb, peer);
    if (tid < 128) {
        remH0 = mapa_u32(smem_u32(&hbuf[0][rank * 128 + tid]), peer);
        remH1 = mapa_u32(smem_u32(&hbuf[1][rank * 128 + tid]), peer);
    }

    const int xcol  = d * Hh + (int)rank * 128 + tid;   // valid for tid<128
    const int dstep = (d ? -1 : 1) * (Bsz * NOUT);
    const float* xp = g_xp + (size_t)(d ? (Tt - 1) : 0) * (Bsz * NOUT)
                           + (size_t)b * NOUT + xcol;
    float xv = (tid < 128) ? __ldg(xp) : 0.0f;

    const int ktile = xcol >> 6;
    const uint32_t ccol = (uint32_t)((xcol & 63) * 2);

    int cur = 0;
    uint32_t ph = 0;

    #pragma unroll 1
    for (int s = 0; s < Tt; s++) {
        ull a0 = 0ull, a1 = 0ull, a2 = 0ull, a3 = 0ull;
        const ulonglong2* hp = (const ulonglong2*)&hbuf[cur][c * 128];
        #pragma unroll
        for (int q = 0; q < 32; q += 2) {
            ulonglong2 h0 = hp[q];
            ulonglong2 h1 = hp[q + 1];
            ffma2(a0, wreg[2 * q],     h0.x);
            ffma2(a1, wreg[2 * q + 1], h0.y);
            ffma2(a2, wreg[2 * q + 2], h1.x);
            ffma2(a3, wreg[2 * q + 3], h1.y);
        }
        float2 p0 = up2(a0), p1 = up2(a1), p2 = up2(a2), p3 = up2(a3);
        part[tid] = ((p0.x + p0.y) + (p1.x + p1.y))
                  + ((p2.x + p2.y) + (p3.x + p3.y));
        __syncthreads();

        if (tid < 128) {
            const float z = part[tid] + part[tid + 128] + xv;
            const float h = tanh_acc(z);
            const int t = d ? (Tt - 1 - s) : s;
            const int nb = cur ^ 1;

            hbuf[nb][rank * 128 + tid] = h;
            st_remote_f32(nb ? remH1 : remH0, h);
            mbar_arrive_rel_cluster(remMb);

            if (store_mode == 0) {
                const int m = t * Bsz + b;
                const int mt2 = m >> 7, r = m & 127;
                const size_t tb = (size_t)(mt2 * NKT1 + ktile) * TILEB;
                const uint32_t off = swz((uint32_t)(r * 128) + ccol);
                __nv_bfloat16 hi = __float2bfloat16_rn(h);
                __nv_bfloat16 lo = __float2bfloat16_rn(h - __bfloat162float(hi));
                *(__nv_bfloat16*)((char*)g_H1hi + tb + off) = hi;
                *(__nv_bfloat16*)((char*)g_H1lo + tb + off) = lo;
            } else {
                outp[((size_t)b * Tt + t) * NOUT + xcol] = h;
            }

            if (s + 1 < Tt) {
                xp += dstep;
                xv = __ldg(xp);
            }
        }
        __syncthreads();
        mbar_wait_acq_cluster(mb, ph);
        ph ^= 1u;
        cur ^= 1;
    }

    asm volatile("barrier.cluster.arrive.aligned;" ::: "memory");
    asm volatile("barrier.cluster.wait.aligned;" ::: "memory");
}

// ---------------------------------------------------------------------------
// Launch
// ---------------------------------------------------------------------------
extern "C" void kernel_launch(void* const* d_in, const int* in_sizes, int n_in,
                              void* d_out, int out_size)
{
    (void)in_sizes; (void)n_in; (void)out_size;
    const float* x    = (const float*)d_in[0];
    const float* Wih0 = (const float*)d_in[1];
    const float* Whh0 = (const float*)d_in[2];
    const float* bih0 = (const float*)d_in[3];
    const float* bhh0 = (const float*)d_in[4];
    const float* Wih1 = (const float*)d_in[5];
    const float* Whh1 = (const float*)d_in[6];
    const float* bih1 = (const float*)d_in[7];
    const float* bhh1 = (const float*)d_in[8];
    float* out = (float*)d_out;

    __nv_bfloat16 *Ahi_p, *Alo_p, *W0hi_p, *W0lo_p, *H1hi_p, *H1lo_p, *W1hi_p, *W1lo_p;
    cudaGetSymbolAddress((void**)&Ahi_p,  g_Ahi);
    cudaGetSymbolAddress((void**)&Alo_p,  g_Alo);
    cudaGetSymbolAddress((void**)&W0hi_p, g_W0hi);
    cudaGetSymbolAddress((void**)&W0lo_p, g_W0lo);
    cudaGetSymbolAddress((void**)&H1hi_p, g_H1hi);
    cudaGetSymbolAddress((void**)&H1lo_p, g_H1lo);
    cudaGetSymbolAddress((void**)&W1hi_p, g_W1hi);
    cudaGetSymbolAddress((void**)&W1lo_p, g_W1lo);

    cudaFuncSetAttribute(gemm_tc, cudaFuncAttributeMaxDynamicSharedMemorySize,
                         GEMM_SMEM);

    conv_bf16<<<(Mrows * (Ii / 8) + 255) / 256, 256>>>(x, Ahi_p, Alo_p, Ii, 0,
                                                       Mrows * (Ii / 8));
    conv_bf16<<<(NOUT * (Ii / 8) + 255) / 256, 256>>>(Wih0, W0hi_p, W0lo_p, Ii, 1,
                                                      NOUT * (Ii / 8));
    conv_bf16<<<(NOUT * (NOUT / 8) + 255) / 256, 256>>>(Wih1, W1hi_p, W1lo_p, NOUT, 1,
                                                        NOUT * (NOUT / 8));

    dim3 gg(NOUT / 128, Mrows / 128);   // (4, 256)

    gemm_tc<<<gg, 256, GEMM_SMEM>>>(Ahi_p, Alo_p, W0hi_p, W0lo_p, bih0, bhh0, NKT0);
    rnn_scan<<<128, 256>>>(Whh0, nullptr, 0);

    gemm_tc<<<gg, 256, GEMM_SMEM>>>(H1hi_p, H1lo_p, W1hi_p, W1lo_p, bih1, bhh1, NKT1);
    rnn_scan<<<128, 256>>>(Whh1, out, 1);
}